// round 5
// baseline (speedup 1.0000x reference)
#include <cuda_runtime.h>

// Problem constants (fixed: B=65536, T=100, D_CP=2, D_FIN=3, HID=12, D_OUT=2)
#define BT_B 65536
#define BT_T 100

typedef unsigned long long u64;

__device__ __forceinline__ u64 pack2(float lo, float hi) {
    u64 r; asm("mov.b64 %0, {%1, %2};" : "=l"(r) : "f"(lo), "f"(hi)); return r;
}
__device__ __forceinline__ void unpack2(u64 v, float& lo, float& hi) {
    asm("mov.b64 {%0, %1}, %2;" : "=f"(lo), "=f"(hi) : "l"(v));
}
__device__ __forceinline__ u64 fma2(u64 a, u64 b, u64 c) {
    u64 d; asm("fma.rn.f32x2 %0, %1, %2, %3;" : "=l"(d) : "l"(a), "l"(b), "l"(c)); return d;
}
__device__ __forceinline__ float tanhapx(float x) {
    float r; asm("tanh.approx.f32 %0, %1;" : "=f"(r) : "f"(x)); return r;
}

// Two threads cooperate on one batch row (half ∈ {0,1} owns hidden units [6h,6h+6)).
// Partial output dots exchanged via shfl.xor(1); both threads hold full (u,v) state.
// launch_bounds(128,7): regs ≤ 72 so all 1024 blocks fit in ONE wave (7 CTAs/SM).
__global__ __launch_bounds__(128, 7)
void deform_tracker_kernel(const float* __restrict__ cp,     // (B, T, 2)
                           const float* __restrict__ fin,    // (B, T, 3)
                           const float* __restrict__ Wr,     // (5, 12)
                           const float* __restrict__ br,     // (12,)
                           const float* __restrict__ Wo,     // (14, 2)
                           const float* __restrict__ bo,     // (2,)
                           float* __restrict__ out)          // (B, T, 2)
{
    const int gt   = blockIdx.x * blockDim.x + threadIdx.x;  // 0 .. 131071
    const int row  = gt >> 1;
    const int half = gt & 1;
    const int cbase = 6 * half;

    // ---- Register-resident weights (own half of the hidden dim) ----
    u64 Wp[5][3];
    #pragma unroll
    for (int i = 0; i < 5; i++)
        #pragma unroll
        for (int k = 0; k < 3; k++)
            Wp[i][k] = pack2(__ldg(Wr + i * 12 + cbase + 2 * k),
                             __ldg(Wr + i * 12 + cbase + 2 * k + 1));

    float wu[6], wv[6];
    #pragma unroll
    for (int j = 0; j < 6; j++) {
        wu[j] = __ldg(Wo + (2 + cbase + j) * 2 + 0);
        wv[j] = __ldg(Wo + (2 + cbase + j) * 2 + 1);
    }
    const float w00 = __ldg(Wo + 0), w01 = __ldg(Wo + 1);
    const float w10 = __ldg(Wo + 2), w11 = __ldg(Wo + 3);
    const float bo0 = __ldg(bo + 0), bo1 = __ldg(bo + 1);

    // ---- Per-row invariants ----
    const float2 cp0 = *reinterpret_cast<const float2*>(cp + (size_t)row * (BT_T * 2));
    const float c0 = fmaf(cp0.x, w00, fmaf(cp0.y, w10, bo0));
    const float c1 = fmaf(cp0.x, w01, fmaf(cp0.y, w11, bo1));

    // base[k] = br + c0*Wr0 + c1*Wr1 (constant part of the fed-back input o = (c0+u, c1+v))
    u64 base[3];
    {
        u64 p0 = pack2(c0, c0), p1 = pack2(c1, c1);
        #pragma unroll
        for (int k = 0; k < 3; k++) {
            u64 brp = pack2(__ldg(br + cbase + 2 * k), __ldg(br + cbase + 2 * k + 1));
            base[k] = fma2(p1, Wp[1][k], fma2(p0, Wp[0][k], brp));
        }
    }

    float u = cp0.x - c0, v = cp0.y - c1;

    const float2* fp = reinterpret_cast<const float2*>(fin + (size_t)row * (BT_T * 3));
    float4* op = reinterpret_cast<float4*>(out + (size_t)row * (BT_T * 2));

    // 50 chunks of 2 timesteps. 3 float2 finger loads and one float4 store per chunk;
    // the store alternates between the two pair-threads (identical lockstep results).
    #pragma unroll 1
    for (int c = 0; c < BT_T / 2; c++) {
        float2 g0 = fp[3 * c + 0];
        float2 g1 = fp[3 * c + 1];
        float2 g2 = fp[3 * c + 2];
        float f[6] = {g0.x, g0.y, g1.x, g1.y, g2.x, g2.y};
        float res[4];

        #pragma unroll
        for (int s = 0; s < 2; s++) {
            // Off-chain partial (independent of u,v): base + fin_t @ Wr[2:5]
            u64 px2 = pack2(f[3 * s + 0], f[3 * s + 0]);
            u64 px3 = pack2(f[3 * s + 1], f[3 * s + 1]);
            u64 px4 = pack2(f[3 * s + 2], f[3 * s + 2]);
            u64 part[3];
            #pragma unroll
            for (int k = 0; k < 3; k++)
                part[k] = fma2(px4, Wp[4][k], fma2(px3, Wp[3][k], fma2(px2, Wp[2][k], base[k])));

            // Critical chain: + u*Wr0 + v*Wr1, tanh
            u64 pu = pack2(u, u), pv = pack2(v, v);
            float h[6];
            #pragma unroll
            for (int k = 0; k < 3; k++) {
                u64 a = fma2(pv, Wp[1][k], fma2(pu, Wp[0][k], part[k]));
                float a0, a1;
                unpack2(a, a0, a1);
                h[2 * k + 0] = tanhapx(a0);
                h[2 * k + 1] = tanhapx(a1);
            }

            // Own half of the output dot (split accumulators, depth 3)
            float ua = h[0] * wu[0], ub = h[1] * wu[1];
            float va = h[0] * wv[0], vb = h[1] * wv[1];
            #pragma unroll
            for (int j = 2; j < 6; j += 2) {
                ua = fmaf(h[j],     wu[j],     ua);
                ub = fmaf(h[j + 1], wu[j + 1], ub);
                va = fmaf(h[j],     wv[j],     va);
                vb = fmaf(h[j + 1], wv[j + 1], vb);
            }
            float uo = ua + ub, vo = va + vb;

            // Exchange partner's partial; both threads hold full (u,v)
            float up = __shfl_xor_sync(0xFFFFFFFFu, uo, 1);
            float vp = __shfl_xor_sync(0xFFFFFFFFu, vo, 1);
            u = uo + up;
            v = vo + vp;

            res[2 * s + 0] = c0 + u;
            res[2 * s + 1] = c1 + v;
        }

        // Alternate which pair-thread stores this chunk (results identical in lockstep)
        if (half == (c & 1)) {
            op[c] = make_float4(res[0], res[1], res[2], res[3]);
        }
    }
}

extern "C" void kernel_launch(void* const* d_in, const int* in_sizes, int n_in,
                              void* d_out, int out_size) {
    const float* cp  = (const float*)d_in[0];  // control_point_input (B,T,2)
    const float* fin = (const float*)d_in[1];  // finger_input (B,T,3)
    const float* Wr  = (const float*)d_in[2];  // W_rnn (5,12)
    // d_in[3] = U_rnn — mathematically inert (hidden state reset each step)
    const float* br  = (const float*)d_in[4];  // b_rnn (12,)
    const float* Wo  = (const float*)d_in[5];  // W_out (14,2)
    const float* bo  = (const float*)d_in[6];  // b_out (2,)
    float* out = (float*)d_out;

    const int threads = 128;
    const int total = BT_B * 2;                 // 2 threads per row
    const int blocks = total / threads;         // 1024 = 148 SMs x 7 CTAs (one wave)
    deform_tracker_kernel<<<blocks, threads>>>(cp, fin, Wr, br, Wo, bo, out);
}